// round 14
// baseline (speedup 1.0000x reference)
#include <cuda_runtime.h>
#include <cuda_bf16.h>
#include <math.h>

#define NN 100000
#define EE 1000000
#define DD 64
#define GG 128
#define SB 512
#define NB ((NN + SB - 1) / SB)
#define WFW 8192   // words per weight-fragment matrix (bf16 hi/lo pairs)

// ---------------- scratch (device globals) -----------------------------------
__device__ int   g_deg[NN];
__device__ int   g_flag[NN];
__device__ float g_temb[DD];
__device__ float g_ab[NN * GG];    // two N x 64 ping-pong halves (A | B)
__device__ float g_h0[NN * GG];
__device__ int   g_off[NN + 1];
__device__ int   g_bsum[NB + 1];
__device__ int   g_cur[NN];
__device__ int   g_csr[EE];
__device__ unsigned g_wf[5 * WFW];

// ---------------- small kernels ---------------------------------------------
__global__ void k_init(int* deg, int* flag, int* cur) {
    int i = blockIdx.x * blockDim.x + threadIdx.x;
    if (i < NN) { deg[i] = 0; flag[i] = 0; cur[i] = 0; }
}

__global__ void k_deg(const int* __restrict__ dst, int* deg) {
    int e = blockIdx.x * blockDim.x + threadIdx.x;
    if (e < EE) atomicAdd(&deg[dst[e]], 1);
}

// ---------------- bf16 helpers ------------------------------------------------
__device__ __forceinline__ unsigned pack_bf16(float a, float b) {
    __nv_bfloat162 t = __floats2bfloat162_rn(a, b);
    return *(unsigned*)&t;
}
__device__ __forceinline__ unsigned pack_lo(float a, float b) {
    __nv_bfloat16 ha = __float2bfloat16_rn(a);
    __nv_bfloat16 hb = __float2bfloat16_rn(b);
    return pack_bf16(a - __bfloat162float(ha), b - __bfloat162float(hb));
}
__device__ __forceinline__ void mma16(float* d, const unsigned* a, unsigned b0, unsigned b1) {
    asm volatile("mma.sync.aligned.m16n8k16.row.col.f32.bf16.bf16.f32 "
        "{%0,%1,%2,%3}, {%4,%5,%6,%7}, {%8,%9}, {%0,%1,%2,%3};"
        : "+f"(d[0]), "+f"(d[1]), "+f"(d[2]), "+f"(d[3])
        : "r"(a[0]), "r"(a[1]), "r"(a[2]), "r"(a[3]), "r"(b0), "r"(b1));
}
__device__ __forceinline__ float silu(float v) { return v / (1.0f + __expf(-v)); }

// ---------------- weight prep + temb + flag scatter ---------------------------
__global__ void k_wprep(const float* __restrict__ w0, const float* __restrict__ w1,
                        const float* __restrict__ w2, const float* __restrict__ w3,
                        unsigned* __restrict__ wf,
                        const int* __restrict__ t,
                        const float* __restrict__ tw1, const float* __restrict__ tb1,
                        const float* __restrict__ tw2, const float* __restrict__ tb2,
                        float* __restrict__ temb,
                        const int* __restrict__ anm, int n_anm,
                        const int* __restrict__ nrm, int n_nrm, int* flag) {
    __shared__ float emb[DD];
    __shared__ float h[DD];
    int b = blockIdx.x;
    int tid = threadIdx.x;
    if (b >= 6) {
        int i = (b - 6) * 256 + tid;
        if (i < n_anm) atomicMax(&flag[anm[i]], 1);
        if (i < n_nrm) atomicMax(&flag[nrm[i]], 2);
        return;
    }
    if (b == 5) {
        if (tid < 32) {
            float tv = (float)t[0];
            float freq = expf((float)tid * (-logf(10000.0f) / 31.0f));
            float arg = tv * freq;
            emb[tid] = sinf(arg);
            emb[tid + 32] = cosf(arg);
        }
        __syncthreads();
        if (tid < DD) {
            float acc = tb1[tid];
            #pragma unroll
            for (int k = 0; k < DD; k++) acc += emb[k] * tw1[k * DD + tid];
            acc = acc / (1.0f + expf(-acc));
            h[tid] = acc;
        }
        __syncthreads();
        if (tid < DD) {
            float acc2 = tb2[tid];
            #pragma unroll
            for (int k = 0; k < DD; k++) acc2 += h[k] * tw2[k * DD + tid];
            temb[tid] = acc2;
        }
        return;
    }
    const float* Wg;
    int fout;
    switch (b) {
        case 0: Wg = w0; fout = 128; break;
        case 1: Wg = w1; fout = 64;  break;
        case 2: Wg = w2; fout = 128; break;
        case 3: Wg = w3; fout = 64;  break;
        default: Wg = w3 + 128 * 64; fout = 64; break;
    }
    uint4* out = (uint4*)(wf + b * WFW);
    const int total = WFW / 4;
    int jt = fout / 8;
    for (int p = tid; p < total; p += blockDim.x) {
        int ks = p / (jt * 32);
        int rem = p % (jt * 32);
        int j = rem / 32;
        int ln = rem % 32;
        int col = j * 8 + (ln >> 2);
        int k0 = ks * 16 + (ln & 3) * 2;
        float v0 = __ldg(&Wg[k0 * fout + col]);
        float v1 = __ldg(&Wg[(k0 + 1) * fout + col]);
        float v2 = __ldg(&Wg[(k0 + 8) * fout + col]);
        float v3 = __ldg(&Wg[(k0 + 9) * fout + col]);
        out[p] = make_uint4(pack_bf16(v0, v1), pack_bf16(v2, v3),
                            pack_lo(v0, v1), pack_lo(v2, v3));
    }
}

// ---------------- z0 = (noise + temb + label) * dinv --------------------------
__global__ void k_z0(const float* __restrict__ noise,
                     const float* __restrict__ lemb,
                     const float* __restrict__ temb,
                     const int* __restrict__ flag,
                     const int* __restrict__ deg,
                     float* __restrict__ z) {
    int idx = blockIdx.x * blockDim.x + threadIdx.x;
    if (idx >= NN * (DD / 4)) return;
    int node = idx >> 4;
    int f4 = idx & 15;
    float4 v = ((const float4*)noise)[idx];
    float4 tb = ((const float4*)temb)[f4];
    v.x += tb.x; v.y += tb.y; v.z += tb.z; v.w += tb.w;
    int fl = flag[node];
    if (fl == 1) {
        float4 l = ((const float4*)(lemb + DD))[f4];
        v.x += l.x; v.y += l.y; v.z += l.z; v.w += l.w;
    } else if (fl == 2) {
        float4 l = ((const float4*)lemb)[f4];
        v.x += l.x; v.y += l.y; v.z += l.z; v.w += l.w;
    }
    float di = rsqrtf((float)deg[node] + 1.0f);
    v.x *= di; v.y *= di; v.z *= di; v.w *= di;
    ((float4*)z)[idx] = v;
}

// ---------------- CSR build (2-kernel scan) -----------------------------------
__global__ void k_scan1(const int* __restrict__ deg, int* off, int* bsum) {
    __shared__ int sh[SB];
    int i = blockIdx.x * SB + threadIdx.x;
    int v = (i < NN) ? deg[i] : 0;
    sh[threadIdx.x] = v;
    __syncthreads();
    for (int s = 1; s < SB; s <<= 1) {
        int t = (threadIdx.x >= s) ? sh[threadIdx.x - s] : 0;
        __syncthreads();
        sh[threadIdx.x] += t;
        __syncthreads();
    }
    if (i < NN) off[i] = sh[threadIdx.x] - v;
    if (threadIdx.x == SB - 1) bsum[blockIdx.x] = sh[SB - 1];
}

// scan3m: each block prefix-sums the (<=256) block sums in smem, then applies.
__global__ void k_scan3m(int* off, const int* __restrict__ bsum) {
    __shared__ int sh[256];
    int tid = threadIdx.x;
    int v = (tid < NB) ? bsum[tid] : 0;
    sh[tid] = v;
    __syncthreads();
    #pragma unroll
    for (int s = 1; s < 256; s <<= 1) {
        int t = (tid >= s) ? sh[tid - s] : 0;
        __syncthreads();
        sh[tid] += t;
        __syncthreads();
    }
    int i = blockIdx.x * blockDim.x + tid;
    if (i < NN) {
        int blk = i / SB;
        int pfx = (blk == 0) ? 0 : sh[blk - 1];
        off[i] += pfx;
    }
    if (i == 0) off[NN] = EE;
}

__global__ void k_fill(const int* __restrict__ src, const int* __restrict__ dst,
                       const int* __restrict__ off, int* cur, int* csr) {
    int e = blockIdx.x * blockDim.x + threadIdx.x;
    if (e < EE) {
        int d = dst[e];
        int p = off[d] + atomicAdd(&cur[d], 1);
        csr[p] = src[e];
    }
}

// ---------------- fused 2-stage MMA kernel (512 threads) -----------------------
// Stage 1: T = silu(X[64x64] * WA[64x128] + bias1)  (T in smem as bf16 hi/lo;
//          if !CONCAT also written to H0 global)
// Stage 2: Y = (T * WB[128x64] [+ H0 * WC[128x64] if CONCAT]) * dinv
template <bool CONCAT>
__global__ void __launch_bounds__(512, 2) k_fused(const float* __restrict__ X,
                                                  const unsigned* __restrict__ wfA,
                                                  const unsigned* __restrict__ wfB,
                                                  const unsigned* __restrict__ wfC,
                                                  float* __restrict__ H0,
                                                  float* __restrict__ Y,
                                                  const int* __restrict__ deg,
                                                  const float* __restrict__ bias1) {
    constexpr int BM = 64;
    constexpr int XROW = 68;    // 32 hi + 32 lo + pad
    constexpr int TROW = 132;   // 64 hi + 64 lo + pad
    __shared__ unsigned S[BM * TROW];

    int tid = threadIdx.x;
    int lane = tid & 31, wid = tid >> 5;   // 16 warps
    int base = blockIdx.x * BM;

    // ---- stage 1: stage X (64x64) as bf16 hi/lo ----
    #pragma unroll
    for (int i = 0; i < 2; i++) {
        int q = tid + i * 512;
        int r = q >> 4, qq = q & 15;
        int gr = base + r; if (gr >= NN) gr = NN - 1;
        float4 v = *(const float4*)&X[(size_t)gr * 64 + qq * 4];
        unsigned* row = S + r * XROW;
        row[qq * 2]          = pack_bf16(v.x, v.y);
        row[qq * 2 + 1]      = pack_bf16(v.z, v.w);
        row[32 + qq * 2]     = pack_lo(v.x, v.y);
        row[32 + qq * 2 + 1] = pack_lo(v.z, v.w);
    }
    __syncthreads();

    // stage-1: 4 N-warps x 4 M-warps; warp tile 16 rows x 32 cols
    int wx = wid & 3, wy = wid >> 2;
    float acc[4][4];
    #pragma unroll
    for (int j = 0; j < 4; j++)
        #pragma unroll
        for (int q = 0; q < 4; q++) acc[j][q] = 0.f;

    const uint4* WA = (const uint4*)wfA;
    {
        int r = wy * 16 + (lane >> 2);
        const unsigned* rp0 = S + r * XROW;
        const unsigned* rp1 = S + (r + 8) * XROW;
        #pragma unroll
        for (int kl = 0; kl < 64; kl += 16) {
            int ksg = kl >> 4;
            int kp = (kl >> 1) + (lane & 3);
            unsigned ah[4], al[4];
            ah[0] = rp0[kp];      ah[1] = rp1[kp];
            ah[2] = rp0[kp + 4];  ah[3] = rp1[kp + 4];
            al[0] = rp0[kp + 32]; al[1] = rp1[kp + 32];
            al[2] = rp0[kp + 36]; al[3] = rp1[kp + 36];
            #pragma unroll
            for (int j = 0; j < 4; j++) {
                uint4 b = __ldg(&WA[(ksg * 16 + wx * 4 + j) * 32 + lane]);
                mma16(acc[j], al, b.x, b.y);
                mma16(acc[j], ah, b.z, b.w);
                mma16(acc[j], ah, b.x, b.y);
            }
        }
    }
    __syncthreads();   // all warps done reading Xs

    // ---- stage-1 epilogue: silu+bias -> T (smem hi/lo) [+ H0 global] ----
    {
        int rr = wy * 16 + (lane >> 2);
        int rr1 = rr + 8;
        #pragma unroll
        for (int j = 0; j < 4; j++) {
            int c = wx * 32 + j * 8 + 2 * (lane & 3);
            float bx = __ldg(&bias1[c]), by = __ldg(&bias1[c + 1]);
            float v0 = silu(acc[j][0] + bx);
            float v1 = silu(acc[j][1] + by);
            float v2 = silu(acc[j][2] + bx);
            float v3 = silu(acc[j][3] + by);
            int w = c >> 1;
            S[rr * TROW + w]        = pack_bf16(v0, v1);
            S[rr * TROW + 64 + w]   = pack_lo(v0, v1);
            S[rr1 * TROW + w]       = pack_bf16(v2, v3);
            S[rr1 * TROW + 64 + w]  = pack_lo(v2, v3);
            if (!CONCAT) {
                int g0 = base + rr, g1 = base + rr1;
                if (g0 < NN) *(float2*)&H0[(size_t)g0 * 128 + c] = make_float2(v0, v1);
                if (g1 < NN) *(float2*)&H0[(size_t)g1 * 128 + c] = make_float2(v2, v3);
            }
        }
    }
    __syncthreads();

    // ---- stage 2: 4 N-warps x 4 M-warps; warp tile 16 rows x 16 cols ----
    int wx2 = wid & 3, wy2 = wid >> 2;
    int rr = wy2 * 16 + (lane >> 2);
    const unsigned* rp0 = S + rr * TROW;
    const unsigned* rp1 = S + (rr + 8) * TROW;

    float a2[2][4];
    #pragma unroll
    for (int j = 0; j < 2; j++)
        #pragma unroll
        for (int q = 0; q < 4; q++) a2[j][q] = 0.f;

    const uint4* WB = (const uint4*)wfB;
    #pragma unroll
    for (int kl = 0; kl < 128; kl += 16) {
        int ksg = kl >> 4;
        int kp = (kl >> 1) + (lane & 3);
        unsigned ah[4], al[4];
        ah[0] = rp0[kp];      ah[1] = rp1[kp];
        ah[2] = rp0[kp + 4];  ah[3] = rp1[kp + 4];
        al[0] = rp0[64 + kp];     al[1] = rp1[64 + kp];
        al[2] = rp0[64 + kp + 4]; al[3] = rp1[64 + kp + 4];
        #pragma unroll
        for (int j = 0; j < 2; j++) {
            uint4 b = __ldg(&WB[(ksg * 8 + wx2 * 2 + j) * 32 + lane]);
            mma16(a2[j], al, b.x, b.y);
            mma16(a2[j], ah, b.z, b.w);
            mma16(a2[j], ah, b.x, b.y);
        }
    }

    if (CONCAT) {
        const uint4* WC = (const uint4*)wfC;
        int g0 = base + rr;       if (g0 >= NN) g0 = NN - 1;
        int g1 = base + rr + 8;   if (g1 >= NN) g1 = NN - 1;
        #pragma unroll
        for (int kl = 0; kl < 128; kl += 16) {
            int ksg = kl >> 4;
            int k0 = kl + (lane & 3) * 2;
            float2 f0 = *(const float2*)&H0[(size_t)g0 * 128 + k0];
            float2 f1 = *(const float2*)&H0[(size_t)g1 * 128 + k0];
            float2 f2 = *(const float2*)&H0[(size_t)g0 * 128 + k0 + 8];
            float2 f3 = *(const float2*)&H0[(size_t)g1 * 128 + k0 + 8];
            unsigned ah[4], al[4];
            ah[0] = pack_bf16(f0.x, f0.y); al[0] = pack_lo(f0.x, f0.y);
            ah[1] = pack_bf16(f1.x, f1.y); al[1] = pack_lo(f1.x, f1.y);
            ah[2] = pack_bf16(f2.x, f2.y); al[2] = pack_lo(f2.x, f2.y);
            ah[3] = pack_bf16(f3.x, f3.y); al[3] = pack_lo(f3.x, f3.y);
            #pragma unroll
            for (int j = 0; j < 2; j++) {
                uint4 b = __ldg(&WC[(ksg * 8 + wx2 * 2 + j) * 32 + lane]);
                mma16(a2[j], al, b.x, b.y);
                mma16(a2[j], ah, b.z, b.w);
                mma16(a2[j], ah, b.x, b.y);
            }
        }
    }

    // ---- stage-2 epilogue: Y = a2 * dinv ----
    int r0 = base + rr, r1 = r0 + 8;
    float s0 = (r0 < NN) ? rsqrtf((float)deg[r0] + 1.0f) : 0.f;
    float s1 = (r1 < NN) ? rsqrtf((float)deg[r1] + 1.0f) : 0.f;
    #pragma unroll
    for (int j = 0; j < 2; j++) {
        int c = wx2 * 16 + j * 8 + 2 * (lane & 3);
        if (r0 < NN)
            *(float2*)&Y[(size_t)r0 * 64 + c] = make_float2(a2[j][0] * s0, a2[j][1] * s0);
        if (r1 < NN)
            *(float2*)&Y[(size_t)r1 * 64 + c] = make_float2(a2[j][2] * s1, a2[j][3] * s1);
    }
}

// ---------------- 64-wide gather ----------------------------------------------
// MODE 0: out = dinv*(sum z[src] + z[i])
// MODE 1: out = silu(dinv*(sum y[src] + y[i]) + b)
// MODE 2: out = silu(dinv*(sum y[src] + y[i]) + b) * dinv
template <int MODE>
__global__ void __launch_bounds__(256) k_gather64(const float* __restrict__ y,
                                                  const int* __restrict__ off,
                                                  const int* __restrict__ csr,
                                                  const int* __restrict__ deg,
                                                  const float* __restrict__ b,
                                                  float* __restrict__ out) {
    int warp = (blockIdx.x * 256 + threadIdx.x) >> 5;
    int lane = threadIdx.x & 31;
    if (warp >= NN) return;
    int beg = off[warp], end = off[warp + 1];
    float a0, a1;
    {
        float2 t = *(const float2*)(y + (size_t)warp * DD + lane * 2);
        a0 = t.x; a1 = t.y;
    }
    for (int eb = beg; eb < end; eb += 32) {
        int n = end - eb; if (n > 32) n = 32;
        int s = (lane < n) ? __ldg(&csr[eb + lane]) : 0;
        int j = 0;
        for (; j + 4 <= n; j += 4) {
            int s0 = __shfl_sync(0xffffffffu, s, j);
            int s1 = __shfl_sync(0xffffffffu, s, j + 1);
            int s2 = __shfl_sync(0xffffffffu, s, j + 2);
            int s3 = __shfl_sync(0xffffffffu, s, j + 3);
            float2 t0 = *(const float2*)(y + (size_t)s0 * DD + lane * 2);
            float2 t1 = *(const float2*)(y + (size_t)s1 * DD + lane * 2);
            float2 t2 = *(const float2*)(y + (size_t)s2 * DD + lane * 2);
            float2 t3 = *(const float2*)(y + (size_t)s3 * DD + lane * 2);
            a0 += (t0.x + t1.x) + (t2.x + t3.x);
            a1 += (t0.y + t1.y) + (t2.y + t3.y);
        }
        for (; j < n; j++) {
            int sj = __shfl_sync(0xffffffffu, s, j);
            float2 t = *(const float2*)(y + (size_t)sj * DD + lane * 2);
            a0 += t.x; a1 += t.y;
        }
    }
    float di = rsqrtf((float)deg[warp] + 1.0f);
    float o0, o1;
    if (MODE == 0) {
        o0 = di * a0; o1 = di * a1;
    } else {
        float v0 = di * a0 + b[lane * 2];
        float v1 = di * a1 + b[lane * 2 + 1];
        o0 = silu(v0);
        o1 = silu(v1);
        if (MODE == 2) { o0 *= di; o1 *= di; }
    }
    *(float2*)(out + (size_t)warp * DD + lane * 2) = make_float2(o0, o1);
}

// ---------------- launch ----------------------------------------------------
extern "C" void kernel_launch(void* const* d_in, const int* in_sizes, int n_in,
                              void* d_out, int out_size) {
    const float* noise_x   = (const float*)d_in[0];
    const int*   edge      = (const int*)d_in[1];
    const int*   t_in      = (const int*)d_in[2];
    const int*   train_anm = (const int*)d_in[3];
    const int*   train_nrm = (const int*)d_in[4];
    const float* time_w1   = (const float*)d_in[5];
    const float* time_b1   = (const float*)d_in[6];
    const float* time_w2   = (const float*)d_in[7];
    const float* time_b2   = (const float*)d_in[8];
    const float* label_emb = (const float*)d_in[9];
    const float* w0 = (const float*)d_in[10];
    const float* b0 = (const float*)d_in[11];
    const float* w1 = (const float*)d_in[12];
    const float* b1 = (const float*)d_in[13];
    const float* w2 = (const float*)d_in[14];
    const float* b2 = (const float*)d_in[15];
    const float* w3 = (const float*)d_in[16];
    const float* b3 = (const float*)d_in[17];
    float* out = (float*)d_out;

    const int* src = edge;
    const int* dst = edge + EE;
    int n_anm = in_sizes[3];
    int n_nrm = in_sizes[4];
    int n_fl = (n_anm > n_nrm) ? n_anm : n_nrm;

    float *p_temb, *p_ab, *p_h0;
    int *p_deg, *p_flag, *p_off, *p_bsum, *p_cur, *p_csr;
    unsigned *p_wf;
    cudaGetSymbolAddress((void**)&p_temb, g_temb);
    cudaGetSymbolAddress((void**)&p_ab,   g_ab);
    cudaGetSymbolAddress((void**)&p_h0,   g_h0);
    cudaGetSymbolAddress((void**)&p_deg,  g_deg);
    cudaGetSymbolAddress((void**)&p_flag, g_flag);
    cudaGetSymbolAddress((void**)&p_off,  g_off);
    cudaGetSymbolAddress((void**)&p_bsum, g_bsum);
    cudaGetSymbolAddress((void**)&p_cur,  g_cur);
    cudaGetSymbolAddress((void**)&p_csr,  g_csr);
    cudaGetSymbolAddress((void**)&p_wf,   g_wf);

    float* A = p_ab;                 // N x 64
    float* B = p_ab + (size_t)NN * DD;

    const int TB = 256;
    const int GBF = (NN + 63) / 64;
    const int GGATH = (NN * 32 + TB - 1) / TB;

    k_init<<<(NN + TB - 1) / TB, TB>>>(p_deg, p_flag, p_cur);
    k_deg<<<(EE + TB - 1) / TB, TB>>>(dst, p_deg);
    k_wprep<<<6 + (n_fl + 255) / 256, 256>>>(w0, w1, w2, w3, p_wf,
                        t_in, time_w1, time_b1, time_w2, time_b2, p_temb,
                        train_anm, n_anm, train_nrm, n_nrm, p_flag);
    k_z0<<<(NN * 16 + TB - 1) / TB, TB>>>(noise_x, label_emb, p_temb, p_flag, p_deg, A);

    // ---- CSR build ----
    k_scan1<<<NB, SB>>>(p_deg, p_off, p_bsum);
    k_scan3m<<<(NN + 255) / 256, 256>>>(p_off, p_bsum);
    k_fill<<<(EE + TB - 1) / TB, TB>>>(src, dst, p_off, p_cur, p_csr);

    // ---- layer 0 aggregate-before: B = dinv*(agg(A)+A) ----
    k_gather64<0><<<GGATH, TB>>>(A, p_off, p_csr, p_deg, 0, B);

    // ---- F01: h0 = silu(B*W0+b0); A = (h0*W1)*dinv ----
    k_fused<false><<<GBF, 512>>>(B, p_wf + 0 * WFW, p_wf + 1 * WFW, 0, p_h0, A, p_deg, b0);

    // ---- layer-1 aggregate-after + layer-2 pre-scale ----
    k_gather64<2><<<GGATH, TB>>>(A, p_off, p_csr, p_deg, b1, B);   // z2
    // ---- layer 2 aggregate-before ----
    k_gather64<0><<<GGATH, TB>>>(B, p_off, p_csr, p_deg, 0, A);    // g2

    // ---- F23: T = silu(A*W2+b2); B = (T*W3a + h0*W3b)*dinv ----
    k_fused<true><<<GBF, 512>>>(A, p_wf + 2 * WFW, p_wf + 3 * WFW, p_wf + 4 * WFW,
                                p_h0, B, p_deg, b2);

    // ---- final aggregate ----
    k_gather64<1><<<GGATH, TB>>>(B, p_off, p_csr, p_deg, b3, out);
}

// round 15
// speedup vs baseline: 1.0619x; 1.0619x over previous
#include <cuda_runtime.h>
#include <cuda_bf16.h>
#include <math.h>

#define NN 100000
#define EE 1000000
#define DD 64
#define GG 128
#define SB 512
#define NB ((NN + SB - 1) / SB)
#define WFW 8192   // words per weight-fragment matrix (bf16 hi/lo pairs)

// ---------------- scratch (device globals) -----------------------------------
__device__ int   g_deg[NN];
__device__ int   g_flag[NN];
__device__ float g_temb[DD];
__device__ float g_ab[NN * GG];    // two N x 64 ping-pong halves (A | B)
__device__ float g_h0[NN * GG];
__device__ int   g_off[NN + 1];
__device__ int   g_bsum[NB + 1];
__device__ int   g_cur[NN];
__device__ int   g_csr[EE];
__device__ unsigned g_wf[5 * WFW];

// ---------------- small kernels ---------------------------------------------
__global__ void k_init(int* deg, int* flag, int* cur) {
    int i = blockIdx.x * blockDim.x + threadIdx.x;
    if (i < NN) { deg[i] = 0; flag[i] = 0; cur[i] = 0; }
}

__global__ void k_deg(const int* __restrict__ dst, int* deg) {
    int e = blockIdx.x * blockDim.x + threadIdx.x;
    if (e < EE) atomicAdd(&deg[dst[e]], 1);
}

// ---------------- bf16 helpers ------------------------------------------------
__device__ __forceinline__ unsigned pack_bf16(float a, float b) {
    __nv_bfloat162 t = __floats2bfloat162_rn(a, b);
    return *(unsigned*)&t;
}
__device__ __forceinline__ unsigned pack_lo(float a, float b) {
    __nv_bfloat16 ha = __float2bfloat16_rn(a);
    __nv_bfloat16 hb = __float2bfloat16_rn(b);
    return pack_bf16(a - __bfloat162float(ha), b - __bfloat162float(hb));
}
__device__ __forceinline__ void mma16(float* d, const unsigned* a, unsigned b0, unsigned b1) {
    asm volatile("mma.sync.aligned.m16n8k16.row.col.f32.bf16.bf16.f32 "
        "{%0,%1,%2,%3}, {%4,%5,%6,%7}, {%8,%9}, {%0,%1,%2,%3};"
        : "+f"(d[0]), "+f"(d[1]), "+f"(d[2]), "+f"(d[3])
        : "r"(a[0]), "r"(a[1]), "r"(a[2]), "r"(a[3]), "r"(b0), "r"(b1));
}
__device__ __forceinline__ float silu(float v) { return v / (1.0f + __expf(-v)); }

// ---------------- weight prep + temb + flag scatter ---------------------------
__global__ void k_wprep(const float* __restrict__ w0, const float* __restrict__ w1,
                        const float* __restrict__ w2, const float* __restrict__ w3,
                        unsigned* __restrict__ wf,
                        const int* __restrict__ t,
                        const float* __restrict__ tw1, const float* __restrict__ tb1,
                        const float* __restrict__ tw2, const float* __restrict__ tb2,
                        float* __restrict__ temb,
                        const int* __restrict__ anm, int n_anm,
                        const int* __restrict__ nrm, int n_nrm, int* flag) {
    __shared__ float emb[DD];
    __shared__ float h[DD];
    int b = blockIdx.x;
    int tid = threadIdx.x;
    if (b >= 6) {
        int i = (b - 6) * 256 + tid;
        if (i < n_anm) atomicMax(&flag[anm[i]], 1);
        if (i < n_nrm) atomicMax(&flag[nrm[i]], 2);
        return;
    }
    if (b == 5) {
        if (tid < 32) {
            float tv = (float)t[0];
            float freq = expf((float)tid * (-logf(10000.0f) / 31.0f));
            float arg = tv * freq;
            emb[tid] = sinf(arg);
            emb[tid + 32] = cosf(arg);
        }
        __syncthreads();
        if (tid < DD) {
            float acc = tb1[tid];
            #pragma unroll
            for (int k = 0; k < DD; k++) acc += emb[k] * tw1[k * DD + tid];
            acc = acc / (1.0f + expf(-acc));
            h[tid] = acc;
        }
        __syncthreads();
        if (tid < DD) {
            float acc2 = tb2[tid];
            #pragma unroll
            for (int k = 0; k < DD; k++) acc2 += h[k] * tw2[k * DD + tid];
            temb[tid] = acc2;
        }
        return;
    }
    const float* Wg;
    int fout;
    switch (b) {
        case 0: Wg = w0; fout = 128; break;
        case 1: Wg = w1; fout = 64;  break;
        case 2: Wg = w2; fout = 128; break;
        case 3: Wg = w3; fout = 64;  break;
        default: Wg = w3 + 128 * 64; fout = 64; break;
    }
    uint4* out = (uint4*)(wf + b * WFW);
    const int total = WFW / 4;
    int jt = fout / 8;
    for (int p = tid; p < total; p += blockDim.x) {
        int ks = p / (jt * 32);
        int rem = p % (jt * 32);
        int j = rem / 32;
        int ln = rem % 32;
        int col = j * 8 + (ln >> 2);
        int k0 = ks * 16 + (ln & 3) * 2;
        float v0 = __ldg(&Wg[k0 * fout + col]);
        float v1 = __ldg(&Wg[(k0 + 1) * fout + col]);
        float v2 = __ldg(&Wg[(k0 + 8) * fout + col]);
        float v3 = __ldg(&Wg[(k0 + 9) * fout + col]);
        out[p] = make_uint4(pack_bf16(v0, v1), pack_bf16(v2, v3),
                            pack_lo(v0, v1), pack_lo(v2, v3));
    }
}

// ---------------- z0 = (noise + temb + label) * dinv --------------------------
__global__ void k_z0(const float* __restrict__ noise,
                     const float* __restrict__ lemb,
                     const float* __restrict__ temb,
                     const int* __restrict__ flag,
                     const int* __restrict__ deg,
                     float* __restrict__ z) {
    int idx = blockIdx.x * blockDim.x + threadIdx.x;
    if (idx >= NN * (DD / 4)) return;
    int node = idx >> 4;
    int f4 = idx & 15;
    float4 v = ((const float4*)noise)[idx];
    float4 tb = ((const float4*)temb)[f4];
    v.x += tb.x; v.y += tb.y; v.z += tb.z; v.w += tb.w;
    int fl = flag[node];
    if (fl == 1) {
        float4 l = ((const float4*)(lemb + DD))[f4];
        v.x += l.x; v.y += l.y; v.z += l.z; v.w += l.w;
    } else if (fl == 2) {
        float4 l = ((const float4*)lemb)[f4];
        v.x += l.x; v.y += l.y; v.z += l.z; v.w += l.w;
    }
    float di = rsqrtf((float)deg[node] + 1.0f);
    v.x *= di; v.y *= di; v.z *= di; v.w *= di;
    ((float4*)z)[idx] = v;
}

// ---------------- CSR build (2-kernel scan) -----------------------------------
__global__ void k_scan1(const int* __restrict__ deg, int* off, int* bsum) {
    __shared__ int sh[SB];
    int i = blockIdx.x * SB + threadIdx.x;
    int v = (i < NN) ? deg[i] : 0;
    sh[threadIdx.x] = v;
    __syncthreads();
    for (int s = 1; s < SB; s <<= 1) {
        int t = (threadIdx.x >= s) ? sh[threadIdx.x - s] : 0;
        __syncthreads();
        sh[threadIdx.x] += t;
        __syncthreads();
    }
    if (i < NN) off[i] = sh[threadIdx.x] - v;
    if (threadIdx.x == SB - 1) bsum[blockIdx.x] = sh[SB - 1];
}

// scan3m: each block prefix-sums the (<=256) block sums in smem, then applies.
__global__ void k_scan3m(int* off, const int* __restrict__ bsum) {
    __shared__ int sh[256];
    int tid = threadIdx.x;
    int v = (tid < NB) ? bsum[tid] : 0;
    sh[tid] = v;
    __syncthreads();
    #pragma unroll
    for (int s = 1; s < 256; s <<= 1) {
        int t = (tid >= s) ? sh[tid - s] : 0;
        __syncthreads();
        sh[tid] += t;
        __syncthreads();
    }
    int i = blockIdx.x * blockDim.x + tid;
    if (i < NN) {
        int blk = i / SB;
        int pfx = (blk == 0) ? 0 : sh[blk - 1];
        off[i] += pfx;
    }
    if (i == 0) off[NN] = EE;
}

__global__ void k_fill(const int* __restrict__ src, const int* __restrict__ dst,
                       const int* __restrict__ off, int* cur, int* csr) {
    int e = blockIdx.x * blockDim.x + threadIdx.x;
    if (e < EE) {
        int d = dst[e];
        int p = off[d] + atomicAdd(&cur[d], 1);
        csr[p] = src[e];
    }
}

// ---------------- fused 2-stage MMA kernel (256 threads) -----------------------
// Stage 1: T = silu(X[64x64] * WA[64x128] + bias1)  (T in smem as bf16 hi/lo;
//          if !CONCAT also written to H0 global)
// Stage 2: Y = (T * WB[128x64] [+ H0 * WC[128x64] if CONCAT]) * dinv
template <bool CONCAT>
__global__ void __launch_bounds__(256) k_fused(const float* __restrict__ X,
                                               const unsigned* __restrict__ wfA,
                                               const unsigned* __restrict__ wfB,
                                               const unsigned* __restrict__ wfC,
                                               float* __restrict__ H0,
                                               float* __restrict__ Y,
                                               const int* __restrict__ deg,
                                               const float* __restrict__ bias1) {
    constexpr int BM = 64;
    constexpr int XROW = 68;    // 32 hi + 32 lo + pad
    constexpr int TROW = 132;   // 64 hi + 64 lo + pad
    __shared__ unsigned S[BM * TROW];

    int tid = threadIdx.x;
    int lane = tid & 31, wid = tid >> 5;
    int base = blockIdx.x * BM;

    // ---- stage 1: stage X (BMx64) as bf16 hi/lo ----
    #pragma unroll
    for (int i = 0; i < 4; i++) {
        int q = tid + i * 256;
        int r = q >> 4, qq = q & 15;
        int gr = base + r; if (gr >= NN) gr = NN - 1;
        float4 v = *(const float4*)&X[(size_t)gr * 64 + qq * 4];
        unsigned* row = S + r * XROW;
        row[qq * 2]          = pack_bf16(v.x, v.y);
        row[qq * 2 + 1]      = pack_bf16(v.z, v.w);
        row[32 + qq * 2]     = pack_lo(v.x, v.y);
        row[32 + qq * 2 + 1] = pack_lo(v.z, v.w);
    }
    __syncthreads();

    int wx = wid & 3, wy = wid >> 2;
    float acc[2][4][4];
    #pragma unroll
    for (int mi = 0; mi < 2; mi++)
        #pragma unroll
        for (int j = 0; j < 4; j++)
            #pragma unroll
            for (int q = 0; q < 4; q++) acc[mi][j][q] = 0.f;

    const uint4* WA = (const uint4*)wfA;
    #pragma unroll
    for (int kl = 0; kl < 64; kl += 16) {
        int ksg = kl >> 4;
        unsigned ah[2][4], al[2][4];
        #pragma unroll
        for (int mi = 0; mi < 2; mi++) {
            int r = wy * 32 + mi * 16 + (lane >> 2);
            int kp = (kl >> 1) + (lane & 3);
            const unsigned* rp0 = S + r * XROW;
            const unsigned* rp1 = S + (r + 8) * XROW;
            ah[mi][0] = rp0[kp];      ah[mi][1] = rp1[kp];
            ah[mi][2] = rp0[kp + 4];  ah[mi][3] = rp1[kp + 4];
            al[mi][0] = rp0[kp + 32]; al[mi][1] = rp1[kp + 32];
            al[mi][2] = rp0[kp + 36]; al[mi][3] = rp1[kp + 36];
        }
        #pragma unroll
        for (int j = 0; j < 4; j++) {
            uint4 b = __ldg(&WA[(ksg * 16 + wx * 4 + j) * 32 + lane]);
            #pragma unroll
            for (int mi = 0; mi < 2; mi++) {
                mma16(acc[mi][j], al[mi], b.x, b.y);
                mma16(acc[mi][j], ah[mi], b.z, b.w);
                mma16(acc[mi][j], ah[mi], b.x, b.y);
            }
        }
    }
    __syncthreads();

    // ---- stage-1 epilogue: silu+bias -> T (smem hi/lo) [+ H0 global] ----
    #pragma unroll
    for (int mi = 0; mi < 2; mi++) {
        int rr = wy * 32 + mi * 16 + (lane >> 2);
        int rr1 = rr + 8;
        #pragma unroll
        for (int j = 0; j < 4; j++) {
            int c = wx * 32 + j * 8 + 2 * (lane & 3);
            float bx = __ldg(&bias1[c]), by = __ldg(&bias1[c + 1]);
            float v0 = silu(acc[mi][j][0] + bx);
            float v1 = silu(acc[mi][j][1] + by);
            float v2 = silu(acc[mi][j][2] + bx);
            float v3 = silu(acc[mi][j][3] + by);
            int w = c >> 1;
            S[rr * TROW + w]        = pack_bf16(v0, v1);
            S[rr * TROW + 64 + w]   = pack_lo(v0, v1);
            S[rr1 * TROW + w]       = pack_bf16(v2, v3);
            S[rr1 * TROW + 64 + w]  = pack_lo(v2, v3);
            if (!CONCAT) {
                int g0 = base + rr, g1 = base + rr1;
                if (g0 < NN) *(float2*)&H0[(size_t)g0 * 128 + c] = make_float2(v0, v1);
                if (g1 < NN) *(float2*)&H0[(size_t)g1 * 128 + c] = make_float2(v2, v3);
            }
        }
    }
    __syncthreads();

    // ---- stage 2: 2 N-warps x 4 M-warps (FOUT=64, BM=64) ----
    int wx2 = wid & 1, wy2 = wid >> 1;
    int rr = wy2 * 16 + (lane >> 2);
    const unsigned* rp0 = S + rr * TROW;
    const unsigned* rp1 = S + (rr + 8) * TROW;

    float a2[4][4];
    #pragma unroll
    for (int j = 0; j < 4; j++)
        #pragma unroll
        for (int q = 0; q < 4; q++) a2[j][q] = 0.f;

    const uint4* WB = (const uint4*)wfB;
    #pragma unroll
    for (int kl = 0; kl < 128; kl += 16) {
        int ksg = kl >> 4;
        int kp = (kl >> 1) + (lane & 3);
        unsigned ah[4], al[4];
        ah[0] = rp0[kp];      ah[1] = rp1[kp];
        ah[2] = rp0[kp + 4];  ah[3] = rp1[kp + 4];
        al[0] = rp0[64 + kp];     al[1] = rp1[64 + kp];
        al[2] = rp0[64 + kp + 4]; al[3] = rp1[64 + kp + 4];
        #pragma unroll
        for (int j = 0; j < 4; j++) {
            uint4 b = __ldg(&WB[(ksg * 8 + wx2 * 4 + j) * 32 + lane]);
            mma16(a2[j], al, b.x, b.y);
            mma16(a2[j], ah, b.z, b.w);
            mma16(a2[j], ah, b.x, b.y);
        }
    }

    if (CONCAT) {
        const uint4* WC = (const uint4*)wfC;
        int g0 = base + rr;       if (g0 >= NN) g0 = NN - 1;
        int g1 = base + rr + 8;   if (g1 >= NN) g1 = NN - 1;
        #pragma unroll
        for (int kl = 0; kl < 128; kl += 16) {
            int ksg = kl >> 4;
            int k0 = kl + (lane & 3) * 2;
            float2 f0 = *(const float2*)&H0[(size_t)g0 * 128 + k0];
            float2 f1 = *(const float2*)&H0[(size_t)g1 * 128 + k0];
            float2 f2 = *(const float2*)&H0[(size_t)g0 * 128 + k0 + 8];
            float2 f3 = *(const float2*)&H0[(size_t)g1 * 128 + k0 + 8];
            unsigned ah[4], al[4];
            ah[0] = pack_bf16(f0.x, f0.y); al[0] = pack_lo(f0.x, f0.y);
            ah[1] = pack_bf16(f1.x, f1.y); al[1] = pack_lo(f1.x, f1.y);
            ah[2] = pack_bf16(f2.x, f2.y); al[2] = pack_lo(f2.x, f2.y);
            ah[3] = pack_bf16(f3.x, f3.y); al[3] = pack_lo(f3.x, f3.y);
            #pragma unroll
            for (int j = 0; j < 4; j++) {
                uint4 b = __ldg(&WC[(ksg * 8 + wx2 * 4 + j) * 32 + lane]);
                mma16(a2[j], al, b.x, b.y);
                mma16(a2[j], ah, b.z, b.w);
                mma16(a2[j], ah, b.x, b.y);
            }
        }
    }

    // ---- stage-2 epilogue: Y = a2 * dinv ----
    int r0 = base + rr, r1 = r0 + 8;
    float s0 = (r0 < NN) ? rsqrtf((float)deg[r0] + 1.0f) : 0.f;
    float s1 = (r1 < NN) ? rsqrtf((float)deg[r1] + 1.0f) : 0.f;
    #pragma unroll
    for (int j = 0; j < 4; j++) {
        int c = wx2 * 32 + j * 8 + 2 * (lane & 3);
        if (r0 < NN)
            *(float2*)&Y[(size_t)r0 * 64 + c] = make_float2(a2[j][0] * s0, a2[j][1] * s0);
        if (r1 < NN)
            *(float2*)&Y[(size_t)r1 * 64 + c] = make_float2(a2[j][2] * s1, a2[j][3] * s1);
    }
}

// ---------------- 64-wide gather ----------------------------------------------
// MODE 0: out = dinv*(sum z[src] + z[i])
// MODE 1: out = silu(dinv*(sum y[src] + y[i]) + b)
// MODE 2: out = silu(dinv*(sum y[src] + y[i]) + b) * dinv
template <int MODE>
__global__ void __launch_bounds__(256) k_gather64(const float* __restrict__ y,
                                                  const int* __restrict__ off,
                                                  const int* __restrict__ csr,
                                                  const int* __restrict__ deg,
                                                  const float* __restrict__ b,
                                                  float* __restrict__ out) {
    int warp = (blockIdx.x * 256 + threadIdx.x) >> 5;
    int lane = threadIdx.x & 31;
    if (warp >= NN) return;
    int beg = off[warp], end = off[warp + 1];
    float a0, a1;
    {
        float2 t = *(const float2*)(y + (size_t)warp * DD + lane * 2);
        a0 = t.x; a1 = t.y;
    }
    for (int eb = beg; eb < end; eb += 32) {
        int n = end - eb; if (n > 32) n = 32;
        int s = (lane < n) ? __ldg(&csr[eb + lane]) : 0;
        int j = 0;
        for (; j + 4 <= n; j += 4) {
            int s0 = __shfl_sync(0xffffffffu, s, j);
            int s1 = __shfl_sync(0xffffffffu, s, j + 1);
            int s2 = __shfl_sync(0xffffffffu, s, j + 2);
            int s3 = __shfl_sync(0xffffffffu, s, j + 3);
            float2 t0 = *(const float2*)(y + (size_t)s0 * DD + lane * 2);
            float2 t1 = *(const float2*)(y + (size_t)s1 * DD + lane * 2);
            float2 t2 = *(const float2*)(y + (size_t)s2 * DD + lane * 2);
            float2 t3 = *(const float2*)(y + (size_t)s3 * DD + lane * 2);
            a0 += (t0.x + t1.x) + (t2.x + t3.x);
            a1 += (t0.y + t1.y) + (t2.y + t3.y);
        }
        for (; j < n; j++) {
            int sj = __shfl_sync(0xffffffffu, s, j);
            float2 t = *(const float2*)(y + (size_t)sj * DD + lane * 2);
            a0 += t.x; a1 += t.y;
        }
    }
    float di = rsqrtf((float)deg[warp] + 1.0f);
    float o0, o1;
    if (MODE == 0) {
        o0 = di * a0; o1 = di * a1;
    } else {
        float v0 = di * a0 + b[lane * 2];
        float v1 = di * a1 + b[lane * 2 + 1];
        o0 = silu(v0);
        o1 = silu(v1);
        if (MODE == 2) { o0 *= di; o1 *= di; }
    }
    *(float2*)(out + (size_t)warp * DD + lane * 2) = make_float2(o0, o1);
}

// ---------------- launch ----------------------------------------------------
extern "C" void kernel_launch(void* const* d_in, const int* in_sizes, int n_in,
                              void* d_out, int out_size) {
    const float* noise_x   = (const float*)d_in[0];
    const int*   edge      = (const int*)d_in[1];
    const int*   t_in      = (const int*)d_in[2];
    const int*   train_anm = (const int*)d_in[3];
    const int*   train_nrm = (const int*)d_in[4];
    const float* time_w1   = (const float*)d_in[5];
    const float* time_b1   = (const float*)d_in[6];
    const float* time_w2   = (const float*)d_in[7];
    const float* time_b2   = (const float*)d_in[8];
    const float* label_emb = (const float*)d_in[9];
    const float* w0 = (const float*)d_in[10];
    const float* b0 = (const float*)d_in[11];
    const float* w1 = (const float*)d_in[12];
    const float* b1 = (const float*)d_in[13];
    const float* w2 = (const float*)d_in[14];
    const float* b2 = (const float*)d_in[15];
    const float* w3 = (const float*)d_in[16];
    const float* b3 = (const float*)d_in[17];
    float* out = (float*)d_out;

    const int* src = edge;
    const int* dst = edge + EE;
    int n_anm = in_sizes[3];
    int n_nrm = in_sizes[4];
    int n_fl = (n_anm > n_nrm) ? n_anm : n_nrm;

    float *p_temb, *p_ab, *p_h0;
    int *p_deg, *p_flag, *p_off, *p_bsum, *p_cur, *p_csr;
    unsigned *p_wf;
    cudaGetSymbolAddress((void**)&p_temb, g_temb);
    cudaGetSymbolAddress((void**)&p_ab,   g_ab);
    cudaGetSymbolAddress((void**)&p_h0,   g_h0);
    cudaGetSymbolAddress((void**)&p_deg,  g_deg);
    cudaGetSymbolAddress((void**)&p_flag, g_flag);
    cudaGetSymbolAddress((void**)&p_off,  g_off);
    cudaGetSymbolAddress((void**)&p_bsum, g_bsum);
    cudaGetSymbolAddress((void**)&p_cur,  g_cur);
    cudaGetSymbolAddress((void**)&p_csr,  g_csr);
    cudaGetSymbolAddress((void**)&p_wf,   g_wf);

    float* A = p_ab;                 // N x 64
    float* B = p_ab + (size_t)NN * DD;

    const int TB = 256;
    const int GBF = (NN + 63) / 64;
    const int GGATH = (NN * 32 + TB - 1) / TB;

    k_init<<<(NN + TB - 1) / TB, TB>>>(p_deg, p_flag, p_cur);
    k_deg<<<(EE + TB - 1) / TB, TB>>>(dst, p_deg);
    k_wprep<<<6 + (n_fl + 255) / 256, 256>>>(w0, w1, w2, w3, p_wf,
                        t_in, time_w1, time_b1, time_w2, time_b2, p_temb,
                        train_anm, n_anm, train_nrm, n_nrm, p_flag);
    k_z0<<<(NN * 16 + TB - 1) / TB, TB>>>(noise_x, label_emb, p_temb, p_flag, p_deg, A);

    // ---- CSR build ----
    k_scan1<<<NB, SB>>>(p_deg, p_off, p_bsum);
    k_scan3m<<<(NN + 255) / 256, 256>>>(p_off, p_bsum);
    k_fill<<<(EE + TB - 1) / TB, TB>>>(src, dst, p_off, p_cur, p_csr);

    // ---- layer 0 aggregate-before: B = dinv*(agg(A)+A) ----
    k_gather64<0><<<GGATH, TB>>>(A, p_off, p_csr, p_deg, 0, B);

    // ---- F01: h0 = silu(B*W0+b0); A = (h0*W1)*dinv ----
    k_fused<false><<<GBF, 256>>>(B, p_wf + 0 * WFW, p_wf + 1 * WFW, 0, p_h0, A, p_deg, b0);

    // ---- layer-1 aggregate-after + layer-2 pre-scale ----
    k_gather64<2><<<GGATH, TB>>>(A, p_off, p_csr, p_deg, b1, B);   // z2
    // ---- layer 2 aggregate-before ----
    k_gather64<0><<<GGATH, TB>>>(B, p_off, p_csr, p_deg, 0, A);    // g2

    // ---- F23: T = silu(A*W2+b2); B = (T*W3a + h0*W3b)*dinv ----
    k_fused<true><<<GBF, 256>>>(A, p_wf + 2 * WFW, p_wf + 3 * WFW, p_wf + 4 * WFW,
                                p_h0, B, p_deg, b2);

    // ---- final aggregate ----
    k_gather64<1><<<GGATH, TB>>>(B, p_off, p_csr, p_deg, b3, out);
}

// round 16
// speedup vs baseline: 1.0647x; 1.0026x over previous
#include <cuda_runtime.h>
#include <cuda_bf16.h>
#include <math.h>

#define NN 100000
#define EE 1000000
#define DD 64
#define GG 128
#define SB 512
#define NB ((NN + SB - 1) / SB)
#define WFW 8192   // words per weight-fragment matrix (bf16 hi/lo pairs)

// ---------------- scratch (device globals) -----------------------------------
__device__ int   g_deg[NN];
__device__ int   g_flag[NN];
__device__ float g_temb[DD];
__device__ float g_ab[NN * GG];    // two N x 64 ping-pong halves (A | B)
__device__ float g_h0[NN * GG];
__device__ int   g_off[NN + 1];
__device__ int   g_bsum[NB + 1];
__device__ int   g_cur[NN];
__device__ int   g_csr[EE];
__device__ unsigned g_wf[5 * WFW];

// ---------------- small kernels ---------------------------------------------
__global__ void k_init(int* deg, int* flag, int* cur) {
    int i = blockIdx.x * blockDim.x + threadIdx.x;
    if (i < NN) { deg[i] = 0; flag[i] = 0; cur[i] = 0; }
}

__global__ void k_deg(const int* __restrict__ dst, int* deg) {
    int e = blockIdx.x * blockDim.x + threadIdx.x;
    if (e < EE) atomicAdd(&deg[dst[e]], 1);
}

// ---------------- bf16 helpers ------------------------------------------------
__device__ __forceinline__ unsigned pack_bf16(float a, float b) {
    __nv_bfloat162 t = __floats2bfloat162_rn(a, b);
    return *(unsigned*)&t;
}
__device__ __forceinline__ unsigned pack_lo(float a, float b) {
    __nv_bfloat16 ha = __float2bfloat16_rn(a);
    __nv_bfloat16 hb = __float2bfloat16_rn(b);
    return pack_bf16(a - __bfloat162float(ha), b - __bfloat162float(hb));
}
__device__ __forceinline__ void mma16(float* d, const unsigned* a, unsigned b0, unsigned b1) {
    asm volatile("mma.sync.aligned.m16n8k16.row.col.f32.bf16.bf16.f32 "
        "{%0,%1,%2,%3}, {%4,%5,%6,%7}, {%8,%9}, {%0,%1,%2,%3};"
        : "+f"(d[0]), "+f"(d[1]), "+f"(d[2]), "+f"(d[3])
        : "r"(a[0]), "r"(a[1]), "r"(a[2]), "r"(a[3]), "r"(b0), "r"(b1));
}
__device__ __forceinline__ float silu(float v) { return v / (1.0f + __expf(-v)); }

// ---------------- weight prep + temb + flag scatter ---------------------------
__global__ void k_wprep(const float* __restrict__ w0, const float* __restrict__ w1,
                        const float* __restrict__ w2, const float* __restrict__ w3,
                        unsigned* __restrict__ wf,
                        const int* __restrict__ t,
                        const float* __restrict__ tw1, const float* __restrict__ tb1,
                        const float* __restrict__ tw2, const float* __restrict__ tb2,
                        float* __restrict__ temb,
                        const int* __restrict__ anm, int n_anm,
                        const int* __restrict__ nrm, int n_nrm, int* flag) {
    __shared__ float emb[DD];
    __shared__ float h[DD];
    int b = blockIdx.x;
    int tid = threadIdx.x;
    if (b >= 6) {
        int i = (b - 6) * 256 + tid;
        if (i < n_anm) atomicMax(&flag[anm[i]], 1);
        if (i < n_nrm) atomicMax(&flag[nrm[i]], 2);
        return;
    }
    if (b == 5) {
        if (tid < 32) {
            float tv = (float)t[0];
            float freq = expf((float)tid * (-logf(10000.0f) / 31.0f));
            float arg = tv * freq;
            emb[tid] = sinf(arg);
            emb[tid + 32] = cosf(arg);
        }
        __syncthreads();
        if (tid < DD) {
            float acc = tb1[tid];
            #pragma unroll
            for (int k = 0; k < DD; k++) acc += emb[k] * tw1[k * DD + tid];
            acc = acc / (1.0f + expf(-acc));
            h[tid] = acc;
        }
        __syncthreads();
        if (tid < DD) {
            float acc2 = tb2[tid];
            #pragma unroll
            for (int k = 0; k < DD; k++) acc2 += h[k] * tw2[k * DD + tid];
            temb[tid] = acc2;
        }
        return;
    }
    const float* Wg;
    int fout;
    switch (b) {
        case 0: Wg = w0; fout = 128; break;
        case 1: Wg = w1; fout = 64;  break;
        case 2: Wg = w2; fout = 128; break;
        case 3: Wg = w3; fout = 64;  break;
        default: Wg = w3 + 128 * 64; fout = 64; break;
    }
    uint4* out = (uint4*)(wf + b * WFW);
    const int total = WFW / 4;
    int jt = fout / 8;
    for (int p = tid; p < total; p += blockDim.x) {
        int ks = p / (jt * 32);
        int rem = p % (jt * 32);
        int j = rem / 32;
        int ln = rem % 32;
        int col = j * 8 + (ln >> 2);
        int k0 = ks * 16 + (ln & 3) * 2;
        float v0 = __ldg(&Wg[k0 * fout + col]);
        float v1 = __ldg(&Wg[(k0 + 1) * fout + col]);
        float v2 = __ldg(&Wg[(k0 + 8) * fout + col]);
        float v3 = __ldg(&Wg[(k0 + 9) * fout + col]);
        out[p] = make_uint4(pack_bf16(v0, v1), pack_bf16(v2, v3),
                            pack_lo(v0, v1), pack_lo(v2, v3));
    }
}

// ---------------- z0 = (noise + temb + label) * dinv --------------------------
__global__ void k_z0(const float* __restrict__ noise,
                     const float* __restrict__ lemb,
                     const float* __restrict__ temb,
                     const int* __restrict__ flag,
                     const int* __restrict__ deg,
                     float* __restrict__ z) {
    int idx = blockIdx.x * blockDim.x + threadIdx.x;
    if (idx >= NN * (DD / 4)) return;
    int node = idx >> 4;
    int f4 = idx & 15;
    float4 v = ((const float4*)noise)[idx];
    float4 tb = ((const float4*)temb)[f4];
    v.x += tb.x; v.y += tb.y; v.z += tb.z; v.w += tb.w;
    int fl = flag[node];
    if (fl == 1) {
        float4 l = ((const float4*)(lemb + DD))[f4];
        v.x += l.x; v.y += l.y; v.z += l.z; v.w += l.w;
    } else if (fl == 2) {
        float4 l = ((const float4*)lemb)[f4];
        v.x += l.x; v.y += l.y; v.z += l.z; v.w += l.w;
    }
    float di = rsqrtf((float)deg[node] + 1.0f);
    v.x *= di; v.y *= di; v.z *= di; v.w *= di;
    ((float4*)z)[idx] = v;
}

// ---------------- CSR build (2-kernel scan) -----------------------------------
__global__ void k_scan1(const int* __restrict__ deg, int* off, int* bsum) {
    __shared__ int sh[SB];
    int i = blockIdx.x * SB + threadIdx.x;
    int v = (i < NN) ? deg[i] : 0;
    sh[threadIdx.x] = v;
    __syncthreads();
    for (int s = 1; s < SB; s <<= 1) {
        int t = (threadIdx.x >= s) ? sh[threadIdx.x - s] : 0;
        __syncthreads();
        sh[threadIdx.x] += t;
        __syncthreads();
    }
    if (i < NN) off[i] = sh[threadIdx.x] - v;
    if (threadIdx.x == SB - 1) bsum[blockIdx.x] = sh[SB - 1];
}

// scan3m: each block prefix-sums the (<=256) block sums in smem, then applies.
__global__ void k_scan3m(int* off, const int* __restrict__ bsum) {
    __shared__ int sh[256];
    int tid = threadIdx.x;
    int v = (tid < NB) ? bsum[tid] : 0;
    sh[tid] = v;
    __syncthreads();
    #pragma unroll
    for (int s = 1; s < 256; s <<= 1) {
        int t = (tid >= s) ? sh[tid - s] : 0;
        __syncthreads();
        sh[tid] += t;
        __syncthreads();
    }
    int i = blockIdx.x * blockDim.x + tid;
    if (i < NN) {
        int blk = i / SB;
        int pfx = (blk == 0) ? 0 : sh[blk - 1];
        off[i] += pfx;
    }
    if (i == 0) off[NN] = EE;
}

__global__ void k_fill(const int* __restrict__ src, const int* __restrict__ dst,
                       const int* __restrict__ off, int* cur, int* csr) {
    int e = blockIdx.x * blockDim.x + threadIdx.x;
    if (e < EE) {
        int d = dst[e];
        int p = off[d] + atomicAdd(&cur[d], 1);
        csr[p] = src[e];
    }
}

// ---------------- fused 2-stage MMA kernel (256 threads) -----------------------
// Stage 1: T = silu(X[64x64] * WA[64x128] + bias1)  (T in smem as bf16 hi/lo;
//          if !CONCAT also written to H0 global)
// Stage 2: Y = (T * WB[128x64] [+ H0 * WC[128x64] if CONCAT]) * dinv
template <bool CONCAT>
__global__ void __launch_bounds__(256) k_fused(const float* __restrict__ X,
                                               const unsigned* __restrict__ wfA,
                                               const unsigned* __restrict__ wfB,
                                               const unsigned* __restrict__ wfC,
                                               float* __restrict__ H0,
                                               float* __restrict__ Y,
                                               const int* __restrict__ deg,
                                               const float* __restrict__ bias1) {
    constexpr int BM = 64;
    constexpr int XROW = 68;    // 32 hi + 32 lo + pad
    constexpr int TROW = 132;   // 64 hi + 64 lo + pad
    __shared__ unsigned S[BM * TROW];

    int tid = threadIdx.x;
    int lane = tid & 31, wid = tid >> 5;
    int base = blockIdx.x * BM;

    // ---- stage 1: stage X (BMx64) as bf16 hi/lo ----
    #pragma unroll
    for (int i = 0; i < 4; i++) {
        int q = tid + i * 256;
        int r = q >> 4, qq = q & 15;
        int gr = base + r; if (gr >= NN) gr = NN - 1;
        float4 v = *(const float4*)&X[(size_t)gr * 64 + qq * 4];
        unsigned* row = S + r * XROW;
        row[qq * 2]          = pack_bf16(v.x, v.y);
        row[qq * 2 + 1]      = pack_bf16(v.z, v.w);
        row[32 + qq * 2]     = pack_lo(v.x, v.y);
        row[32 + qq * 2 + 1] = pack_lo(v.z, v.w);
    }
    __syncthreads();

    int wx = wid & 3, wy = wid >> 2;
    float acc[2][4][4];
    #pragma unroll
    for (int mi = 0; mi < 2; mi++)
        #pragma unroll
        for (int j = 0; j < 4; j++)
            #pragma unroll
            for (int q = 0; q < 4; q++) acc[mi][j][q] = 0.f;

    const uint4* WA = (const uint4*)wfA;
    #pragma unroll
    for (int kl = 0; kl < 64; kl += 16) {
        int ksg = kl >> 4;
        unsigned ah[2][4], al[2][4];
        #pragma unroll
        for (int mi = 0; mi < 2; mi++) {
            int r = wy * 32 + mi * 16 + (lane >> 2);
            int kp = (kl >> 1) + (lane & 3);
            const unsigned* rp0 = S + r * XROW;
            const unsigned* rp1 = S + (r + 8) * XROW;
            ah[mi][0] = rp0[kp];      ah[mi][1] = rp1[kp];
            ah[mi][2] = rp0[kp + 4];  ah[mi][3] = rp1[kp + 4];
            al[mi][0] = rp0[kp + 32]; al[mi][1] = rp1[kp + 32];
            al[mi][2] = rp0[kp + 36]; al[mi][3] = rp1[kp + 36];
        }
        #pragma unroll
        for (int j = 0; j < 4; j++) {
            uint4 b = __ldg(&WA[(ksg * 16 + wx * 4 + j) * 32 + lane]);
            #pragma unroll
            for (int mi = 0; mi < 2; mi++) {
                mma16(acc[mi][j], al[mi], b.x, b.y);
                mma16(acc[mi][j], ah[mi], b.z, b.w);
                mma16(acc[mi][j], ah[mi], b.x, b.y);
            }
        }
    }
    __syncthreads();

    // ---- stage-1 epilogue: silu+bias -> T (smem hi/lo) [+ H0 global] ----
    #pragma unroll
    for (int mi = 0; mi < 2; mi++) {
        int rr = wy * 32 + mi * 16 + (lane >> 2);
        int rr1 = rr + 8;
        #pragma unroll
        for (int j = 0; j < 4; j++) {
            int c = wx * 32 + j * 8 + 2 * (lane & 3);
            float bx = __ldg(&bias1[c]), by = __ldg(&bias1[c + 1]);
            float v0 = silu(acc[mi][j][0] + bx);
            float v1 = silu(acc[mi][j][1] + by);
            float v2 = silu(acc[mi][j][2] + bx);
            float v3 = silu(acc[mi][j][3] + by);
            int w = c >> 1;
            S[rr * TROW + w]        = pack_bf16(v0, v1);
            S[rr * TROW + 64 + w]   = pack_lo(v0, v1);
            S[rr1 * TROW + w]       = pack_bf16(v2, v3);
            S[rr1 * TROW + 64 + w]  = pack_lo(v2, v3);
            if (!CONCAT) {
                int g0 = base + rr, g1 = base + rr1;
                if (g0 < NN) *(float2*)&H0[(size_t)g0 * 128 + c] = make_float2(v0, v1);
                if (g1 < NN) *(float2*)&H0[(size_t)g1 * 128 + c] = make_float2(v2, v3);
            }
        }
    }
    __syncthreads();

    // ---- stage 2: 2 N-warps x 4 M-warps (FOUT=64, BM=64) ----
    int wx2 = wid & 1, wy2 = wid >> 1;
    int rr = wy2 * 16 + (lane >> 2);
    const unsigned* rp0 = S + rr * TROW;
    const unsigned* rp1 = S + (rr + 8) * TROW;

    float a2[4][4];
    #pragma unroll
    for (int j = 0; j < 4; j++)
        #pragma unroll
        for (int q = 0; q < 4; q++) a2[j][q] = 0.f;

    const uint4* WB = (const uint4*)wfB;
    #pragma unroll
    for (int kl = 0; kl < 128; kl += 16) {
        int ksg = kl >> 4;
        int kp = (kl >> 1) + (lane & 3);
        unsigned ah[4], al[4];
        ah[0] = rp0[kp];      ah[1] = rp1[kp];
        ah[2] = rp0[kp + 4];  ah[3] = rp1[kp + 4];
        al[0] = rp0[64 + kp];     al[1] = rp1[64 + kp];
        al[2] = rp0[64 + kp + 4]; al[3] = rp1[64 + kp + 4];
        #pragma unroll
        for (int j = 0; j < 4; j++) {
            uint4 b = __ldg(&WB[(ksg * 8 + wx2 * 4 + j) * 32 + lane]);
            mma16(a2[j], al, b.x, b.y);
            mma16(a2[j], ah, b.z, b.w);
            mma16(a2[j], ah, b.x, b.y);
        }
    }

    if (CONCAT) {
        const uint4* WC = (const uint4*)wfC;
        int g0 = base + rr;       if (g0 >= NN) g0 = NN - 1;
        int g1 = base + rr + 8;   if (g1 >= NN) g1 = NN - 1;
        #pragma unroll
        for (int kl = 0; kl < 128; kl += 16) {
            int ksg = kl >> 4;
            int k0 = kl + (lane & 3) * 2;
            float2 f0 = *(const float2*)&H0[(size_t)g0 * 128 + k0];
            float2 f1 = *(const float2*)&H0[(size_t)g1 * 128 + k0];
            float2 f2 = *(const float2*)&H0[(size_t)g0 * 128 + k0 + 8];
            float2 f3 = *(const float2*)&H0[(size_t)g1 * 128 + k0 + 8];
            unsigned ah[4], al[4];
            ah[0] = pack_bf16(f0.x, f0.y); al[0] = pack_lo(f0.x, f0.y);
            ah[1] = pack_bf16(f1.x, f1.y); al[1] = pack_lo(f1.x, f1.y);
            ah[2] = pack_bf16(f2.x, f2.y); al[2] = pack_lo(f2.x, f2.y);
            ah[3] = pack_bf16(f3.x, f3.y); al[3] = pack_lo(f3.x, f3.y);
            #pragma unroll
            for (int j = 0; j < 4; j++) {
                uint4 b = __ldg(&WC[(ksg * 8 + wx2 * 4 + j) * 32 + lane]);
                mma16(a2[j], al, b.x, b.y);
                mma16(a2[j], ah, b.z, b.w);
                mma16(a2[j], ah, b.x, b.y);
            }
        }
    }

    // ---- stage-2 epilogue: Y = a2 * dinv ----
    int r0 = base + rr, r1 = r0 + 8;
    float s0 = (r0 < NN) ? rsqrtf((float)deg[r0] + 1.0f) : 0.f;
    float s1 = (r1 < NN) ? rsqrtf((float)deg[r1] + 1.0f) : 0.f;
    #pragma unroll
    for (int j = 0; j < 4; j++) {
        int c = wx2 * 32 + j * 8 + 2 * (lane & 3);
        if (r0 < NN)
            *(float2*)&Y[(size_t)r0 * 64 + c] = make_float2(a2[j][0] * s0, a2[j][1] * s0);
        if (r1 < NN)
            *(float2*)&Y[(size_t)r1 * 64 + c] = make_float2(a2[j][2] * s1, a2[j][3] * s1);
    }
}

// ---------------- 64-wide gather ----------------------------------------------
// MODE 0: out = dinv*(sum z[src] + z[i])
// MODE 1: out = silu(dinv*(sum y[src] + y[i]) + b)
// MODE 2: out = silu(dinv*(sum y[src] + y[i]) + b) * dinv
template <int MODE>
__global__ void __launch_bounds__(256) k_gather64(const float* __restrict__ y,
                                                  const int* __restrict__ off,
                                                  const int* __restrict__ csr,
                                                  const int* __restrict__ deg,
                                                  const float* __restrict__ b,
                                                  float* __restrict__ out) {
    int warp = (blockIdx.x * 256 + threadIdx.x) >> 5;
    int lane = threadIdx.x & 31;
    if (warp >= NN) return;
    int beg = off[warp], end = off[warp + 1];
    float a0, a1;
    {
        float2 t = *(const float2*)(y + (size_t)warp * DD + lane * 2);
        a0 = t.x; a1 = t.y;
    }
    for (int eb = beg; eb < end; eb += 32) {
        int n = end - eb; if (n > 32) n = 32;
        int s = (lane < n) ? __ldg(&csr[eb + lane]) : 0;
        int j = 0;
        for (; j + 4 <= n; j += 4) {
            int s0 = __shfl_sync(0xffffffffu, s, j);
            int s1 = __shfl_sync(0xffffffffu, s, j + 1);
            int s2 = __shfl_sync(0xffffffffu, s, j + 2);
            int s3 = __shfl_sync(0xffffffffu, s, j + 3);
            float2 t0 = *(const float2*)(y + (size_t)s0 * DD + lane * 2);
            float2 t1 = *(const float2*)(y + (size_t)s1 * DD + lane * 2);
            float2 t2 = *(const float2*)(y + (size_t)s2 * DD + lane * 2);
            float2 t3 = *(const float2*)(y + (size_t)s3 * DD + lane * 2);
            a0 += (t0.x + t1.x) + (t2.x + t3.x);
            a1 += (t0.y + t1.y) + (t2.y + t3.y);
        }
        for (; j < n; j++) {
            int sj = __shfl_sync(0xffffffffu, s, j);
            float2 t = *(const float2*)(y + (size_t)sj * DD + lane * 2);
            a0 += t.x; a1 += t.y;
        }
    }
    float di = rsqrtf((float)deg[warp] + 1.0f);
    float o0, o1;
    if (MODE == 0) {
        o0 = di * a0; o1 = di * a1;
    } else {
        float v0 = di * a0 + b[lane * 2];
        float v1 = di * a1 + b[lane * 2 + 1];
        o0 = silu(v0);
        o1 = silu(v1);
        if (MODE == 2) { o0 *= di; o1 *= di; }
    }
    *(float2*)(out + (size_t)warp * DD + lane * 2) = make_float2(o0, o1);
}

// ---------------- launch ----------------------------------------------------
extern "C" void kernel_launch(void* const* d_in, const int* in_sizes, int n_in,
                              void* d_out, int out_size) {
    const float* noise_x   = (const float*)d_in[0];
    const int*   edge      = (const int*)d_in[1];
    const int*   t_in      = (const int*)d_in[2];
    const int*   train_anm = (const int*)d_in[3];
    const int*   train_nrm = (const int*)d_in[4];
    const float* time_w1   = (const float*)d_in[5];
    const float* time_b1   = (const float*)d_in[6];
    const float* time_w2   = (const float*)d_in[7];
    const float* time_b2   = (const float*)d_in[8];
    const float* label_emb = (const float*)d_in[9];
    const float* w0 = (const float*)d_in[10];
    const float* b0 = (const float*)d_in[11];
    const float* w1 = (const float*)d_in[12];
    const float* b1 = (const float*)d_in[13];
    const float* w2 = (const float*)d_in[14];
    const float* b2 = (const float*)d_in[15];
    const float* w3 = (const float*)d_in[16];
    const float* b3 = (const float*)d_in[17];
    float* out = (float*)d_out;

    const int* src = edge;
    const int* dst = edge + EE;
    int n_anm = in_sizes[3];
    int n_nrm = in_sizes[4];
    int n_fl = (n_anm > n_nrm) ? n_anm : n_nrm;

    float *p_temb, *p_ab, *p_h0;
    int *p_deg, *p_flag, *p_off, *p_bsum, *p_cur, *p_csr;
    unsigned *p_wf;
    cudaGetSymbolAddress((void**)&p_temb, g_temb);
    cudaGetSymbolAddress((void**)&p_ab,   g_ab);
    cudaGetSymbolAddress((void**)&p_h0,   g_h0);
    cudaGetSymbolAddress((void**)&p_deg,  g_deg);
    cudaGetSymbolAddress((void**)&p_flag, g_flag);
    cudaGetSymbolAddress((void**)&p_off,  g_off);
    cudaGetSymbolAddress((void**)&p_bsum, g_bsum);
    cudaGetSymbolAddress((void**)&p_cur,  g_cur);
    cudaGetSymbolAddress((void**)&p_csr,  g_csr);
    cudaGetSymbolAddress((void**)&p_wf,   g_wf);

    float* A = p_ab;                 // N x 64
    float* B = p_ab + (size_t)NN * DD;

    const int TB = 256;
    const int GBF = (NN + 63) / 64;
    const int GGATH = (NN * 32 + TB - 1) / TB;

    k_init<<<(NN + TB - 1) / TB, TB>>>(p_deg, p_flag, p_cur);
    k_deg<<<(EE + TB - 1) / TB, TB>>>(dst, p_deg);
    k_wprep<<<6 + (n_fl + 255) / 256, 256>>>(w0, w1, w2, w3, p_wf,
                        t_in, time_w1, time_b1, time_w2, time_b2, p_temb,
                        train_anm, n_anm, train_nrm, n_nrm, p_flag);
    k_z0<<<(NN * 16 + TB - 1) / TB, TB>>>(noise_x, label_emb, p_temb, p_flag, p_deg, A);

    // ---- CSR build ----
    k_scan1<<<NB, SB>>>(p_deg, p_off, p_bsum);
    k_scan3m<<<(NN + 255) / 256, 256>>>(p_off, p_bsum);
    k_fill<<<(EE + TB - 1) / TB, TB>>>(src, dst, p_off, p_cur, p_csr);

    // ---- layer 0 aggregate-before: B = dinv*(agg(A)+A) ----
    k_gather64<0><<<GGATH, TB>>>(A, p_off, p_csr, p_deg, 0, B);

    // ---- F01: h0 = silu(B*W0+b0); A = (h0*W1)*dinv ----
    k_fused<false><<<GBF, 256>>>(B, p_wf + 0 * WFW, p_wf + 1 * WFW, 0, p_h0, A, p_deg, b0);

    // ---- layer-1 aggregate-after + layer-2 pre-scale ----
    k_gather64<2><<<GGATH, TB>>>(A, p_off, p_csr, p_deg, b1, B);   // z2
    // ---- layer 2 aggregate-before ----
    k_gather64<0><<<GGATH, TB>>>(B, p_off, p_csr, p_deg, 0, A);    // g2

    // ---- F23: T = silu(A*W2+b2); B = (T*W3a + h0*W3b)*dinv ----
    k_fused<true><<<GBF, 256>>>(A, p_wf + 2 * WFW, p_wf + 3 * WFW, p_wf + 4 * WFW,
                                p_h0, B, p_deg, b2);

    // ---- final aggregate ----
    k_gather64<1><<<GGATH, TB>>>(B, p_off, p_csr, p_deg, b3, out);
}

// round 17
// speedup vs baseline: 1.0681x; 1.0031x over previous
#include <cuda_runtime.h>
#include <cuda_bf16.h>
#include <math.h>

#define NN 100000
#define EE 1000000
#define DD 64
#define GG 128
#define SB 512
#define NB ((NN + SB - 1) / SB)
#define WFW 8192   // words per weight-fragment matrix (bf16 hi/lo pairs)

// ---------------- scratch (device globals) -----------------------------------
__device__ int   g_deg[NN];
__device__ int   g_flag[NN];
__device__ float g_temb[DD];
__device__ float g_ab[NN * GG];    // two N x 64 ping-pong halves (A | B)
__device__ float g_h0[NN * GG];
__device__ int   g_off[NN + 1];
__device__ int   g_bsum[NB + 1];
__device__ int   g_cur[NN];
__device__ int   g_csr[EE];
__device__ unsigned g_wf[5 * WFW];

// ---------------- small kernels ---------------------------------------------
__global__ void k_init(int* deg, int* flag, int* cur) {
    int i = blockIdx.x * blockDim.x + threadIdx.x;
    if (i < NN) { deg[i] = 0; flag[i] = 0; cur[i] = 0; }
}

__global__ void k_deg(const int* __restrict__ dst, int* deg) {
    int e = blockIdx.x * blockDim.x + threadIdx.x;
    if (e < EE) atomicAdd(&deg[dst[e]], 1);
}

// ---------------- bf16 helpers ------------------------------------------------
__device__ __forceinline__ unsigned pack_bf16(float a, float b) {
    __nv_bfloat162 t = __floats2bfloat162_rn(a, b);
    return *(unsigned*)&t;
}
__device__ __forceinline__ unsigned pack_lo(float a, float b) {
    __nv_bfloat16 ha = __float2bfloat16_rn(a);
    __nv_bfloat16 hb = __float2bfloat16_rn(b);
    return pack_bf16(a - __bfloat162float(ha), b - __bfloat162float(hb));
}
__device__ __forceinline__ void mma16(float* d, const unsigned* a, unsigned b0, unsigned b1) {
    asm volatile("mma.sync.aligned.m16n8k16.row.col.f32.bf16.bf16.f32 "
        "{%0,%1,%2,%3}, {%4,%5,%6,%7}, {%8,%9}, {%0,%1,%2,%3};"
        : "+f"(d[0]), "+f"(d[1]), "+f"(d[2]), "+f"(d[3])
        : "r"(a[0]), "r"(a[1]), "r"(a[2]), "r"(a[3]), "r"(b0), "r"(b1));
}
__device__ __forceinline__ float silu(float v) { return v / (1.0f + __expf(-v)); }

// ---------------- weight prep + temb + flag scatter ---------------------------
__global__ void k_wprep(const float* __restrict__ w0, const float* __restrict__ w1,
                        const float* __restrict__ w2, const float* __restrict__ w3,
                        unsigned* __restrict__ wf,
                        const int* __restrict__ t,
                        const float* __restrict__ tw1, const float* __restrict__ tb1,
                        const float* __restrict__ tw2, const float* __restrict__ tb2,
                        float* __restrict__ temb,
                        const int* __restrict__ anm, int n_anm,
                        const int* __restrict__ nrm, int n_nrm, int* flag) {
    __shared__ float emb[DD];
    __shared__ float h[DD];
    int b = blockIdx.x;
    int tid = threadIdx.x;
    if (b >= 6) {
        int i = (b - 6) * 256 + tid;
        if (i < n_anm) atomicMax(&flag[anm[i]], 1);
        if (i < n_nrm) atomicMax(&flag[nrm[i]], 2);
        return;
    }
    if (b == 5) {
        if (tid < 32) {
            float tv = (float)t[0];
            float freq = expf((float)tid * (-logf(10000.0f) / 31.0f));
            float arg = tv * freq;
            emb[tid] = sinf(arg);
            emb[tid + 32] = cosf(arg);
        }
        __syncthreads();
        if (tid < DD) {
            float acc = tb1[tid];
            #pragma unroll
            for (int k = 0; k < DD; k++) acc += emb[k] * tw1[k * DD + tid];
            acc = acc / (1.0f + expf(-acc));
            h[tid] = acc;
        }
        __syncthreads();
        if (tid < DD) {
            float acc2 = tb2[tid];
            #pragma unroll
            for (int k = 0; k < DD; k++) acc2 += h[k] * tw2[k * DD + tid];
            temb[tid] = acc2;
        }
        return;
    }
    const float* Wg;
    int fout;
    switch (b) {
        case 0: Wg = w0; fout = 128; break;
        case 1: Wg = w1; fout = 64;  break;
        case 2: Wg = w2; fout = 128; break;
        case 3: Wg = w3; fout = 64;  break;
        default: Wg = w3 + 128 * 64; fout = 64; break;
    }
    uint4* out = (uint4*)(wf + b * WFW);
    const int total = WFW / 4;
    int jt = fout / 8;
    for (int p = tid; p < total; p += blockDim.x) {
        int ks = p / (jt * 32);
        int rem = p % (jt * 32);
        int j = rem / 32;
        int ln = rem % 32;
        int col = j * 8 + (ln >> 2);
        int k0 = ks * 16 + (ln & 3) * 2;
        float v0 = __ldg(&Wg[k0 * fout + col]);
        float v1 = __ldg(&Wg[(k0 + 1) * fout + col]);
        float v2 = __ldg(&Wg[(k0 + 8) * fout + col]);
        float v3 = __ldg(&Wg[(k0 + 9) * fout + col]);
        out[p] = make_uint4(pack_bf16(v0, v1), pack_bf16(v2, v3),
                            pack_lo(v0, v1), pack_lo(v2, v3));
    }
}

// ---------------- z0 = (noise + temb + label) * dinv --------------------------
__global__ void k_z0(const float* __restrict__ noise,
                     const float* __restrict__ lemb,
                     const float* __restrict__ temb,
                     const int* __restrict__ flag,
                     const int* __restrict__ deg,
                     float* __restrict__ z) {
    int idx = blockIdx.x * blockDim.x + threadIdx.x;
    if (idx >= NN * (DD / 4)) return;
    int node = idx >> 4;
    int f4 = idx & 15;
    float4 v = ((const float4*)noise)[idx];
    float4 tb = ((const float4*)temb)[f4];
    v.x += tb.x; v.y += tb.y; v.z += tb.z; v.w += tb.w;
    int fl = flag[node];
    if (fl == 1) {
        float4 l = ((const float4*)(lemb + DD))[f4];
        v.x += l.x; v.y += l.y; v.z += l.z; v.w += l.w;
    } else if (fl == 2) {
        float4 l = ((const float4*)lemb)[f4];
        v.x += l.x; v.y += l.y; v.z += l.z; v.w += l.w;
    }
    float di = rsqrtf((float)deg[node] + 1.0f);
    v.x *= di; v.y *= di; v.z *= di; v.w *= di;
    ((float4*)z)[idx] = v;
}

// ---------------- CSR build (2-kernel scan) -----------------------------------
__global__ void k_scan1(const int* __restrict__ deg, int* off, int* bsum) {
    __shared__ int sh[SB];
    int i = blockIdx.x * SB + threadIdx.x;
    int v = (i < NN) ? deg[i] : 0;
    sh[threadIdx.x] = v;
    __syncthreads();
    for (int s = 1; s < SB; s <<= 1) {
        int t = (threadIdx.x >= s) ? sh[threadIdx.x - s] : 0;
        __syncthreads();
        sh[threadIdx.x] += t;
        __syncthreads();
    }
    if (i < NN) off[i] = sh[threadIdx.x] - v;
    if (threadIdx.x == SB - 1) bsum[blockIdx.x] = sh[SB - 1];
}

// scan3m: each block prefix-sums the (<=256) block sums in smem, then applies.
__global__ void k_scan3m(int* off, const int* __restrict__ bsum) {
    __shared__ int sh[256];
    int tid = threadIdx.x;
    int v = (tid < NB) ? bsum[tid] : 0;
    sh[tid] = v;
    __syncthreads();
    #pragma unroll
    for (int s = 1; s < 256; s <<= 1) {
        int t = (tid >= s) ? sh[tid - s] : 0;
        __syncthreads();
        sh[tid] += t;
        __syncthreads();
    }
    int i = blockIdx.x * blockDim.x + tid;
    if (i < NN) {
        int blk = i / SB;
        int pfx = (blk == 0) ? 0 : sh[blk - 1];
        off[i] += pfx;
    }
    if (i == 0) off[NN] = EE;
}

__global__ void k_fill(const int* __restrict__ src, const int* __restrict__ dst,
                       const int* __restrict__ off, int* cur, int* csr) {
    int e = blockIdx.x * blockDim.x + threadIdx.x;
    if (e < EE) {
        int d = dst[e];
        int p = off[d] + atomicAdd(&cur[d], 1);
        csr[p] = src[e];
    }
}

// ---------------- fused 2-stage MMA kernel (256 threads) -----------------------
// Stage 1: T = silu(X[64x64] * WA[64x128] + bias1)  (T in smem as bf16 hi/lo;
//          if !CONCAT also written to H0 global)
// Stage 2: Y = (T * WB[128x64] [+ H0 * WC[128x64] if CONCAT]) * dinv
template <bool CONCAT>
__global__ void __launch_bounds__(256) k_fused(const float* __restrict__ X,
                                               const unsigned* __restrict__ wfA,
                                               const unsigned* __restrict__ wfB,
                                               const unsigned* __restrict__ wfC,
                                               float* __restrict__ H0,
                                               float* __restrict__ Y,
                                               const int* __restrict__ deg,
                                               const float* __restrict__ bias1) {
    constexpr int BM = 64;
    constexpr int XROW = 68;    // 32 hi + 32 lo + pad
    constexpr int TROW = 132;   // 64 hi + 64 lo + pad
    __shared__ unsigned S[BM * TROW];

    int tid = threadIdx.x;
    int lane = tid & 31, wid = tid >> 5;
    int base = blockIdx.x * BM;

    // ---- stage 1: stage X (BMx64) as bf16 hi/lo ----
    #pragma unroll
    for (int i = 0; i < 4; i++) {
        int q = tid + i * 256;
        int r = q >> 4, qq = q & 15;
        int gr = base + r; if (gr >= NN) gr = NN - 1;
        float4 v = *(const float4*)&X[(size_t)gr * 64 + qq * 4];
        unsigned* row = S + r * XROW;
        row[qq * 2]          = pack_bf16(v.x, v.y);
        row[qq * 2 + 1]      = pack_bf16(v.z, v.w);
        row[32 + qq * 2]     = pack_lo(v.x, v.y);
        row[32 + qq * 2 + 1] = pack_lo(v.z, v.w);
    }
    __syncthreads();

    int wx = wid & 3, wy = wid >> 2;
    float acc[2][4][4];
    #pragma unroll
    for (int mi = 0; mi < 2; mi++)
        #pragma unroll
        for (int j = 0; j < 4; j++)
            #pragma unroll
            for (int q = 0; q < 4; q++) acc[mi][j][q] = 0.f;

    const uint4* WA = (const uint4*)wfA;
    #pragma unroll
    for (int kl = 0; kl < 64; kl += 16) {
        int ksg = kl >> 4;
        unsigned ah[2][4], al[2][4];
        #pragma unroll
        for (int mi = 0; mi < 2; mi++) {
            int r = wy * 32 + mi * 16 + (lane >> 2);
            int kp = (kl >> 1) + (lane & 3);
            const unsigned* rp0 = S + r * XROW;
            const unsigned* rp1 = S + (r + 8) * XROW;
            ah[mi][0] = rp0[kp];      ah[mi][1] = rp1[kp];
            ah[mi][2] = rp0[kp + 4];  ah[mi][3] = rp1[kp + 4];
            al[mi][0] = rp0[kp + 32]; al[mi][1] = rp1[kp + 32];
            al[mi][2] = rp0[kp + 36]; al[mi][3] = rp1[kp + 36];
        }
        #pragma unroll
        for (int j = 0; j < 4; j++) {
            uint4 b = __ldg(&WA[(ksg * 16 + wx * 4 + j) * 32 + lane]);
            #pragma unroll
            for (int mi = 0; mi < 2; mi++) {
                mma16(acc[mi][j], al[mi], b.x, b.y);
                mma16(acc[mi][j], ah[mi], b.z, b.w);
                mma16(acc[mi][j], ah[mi], b.x, b.y);
            }
        }
    }
    __syncthreads();

    // ---- stage-1 epilogue: silu+bias -> T (smem hi/lo) [+ H0 global] ----
    #pragma unroll
    for (int mi = 0; mi < 2; mi++) {
        int rr = wy * 32 + mi * 16 + (lane >> 2);
        int rr1 = rr + 8;
        #pragma unroll
        for (int j = 0; j < 4; j++) {
            int c = wx * 32 + j * 8 + 2 * (lane & 3);
            float bx = __ldg(&bias1[c]), by = __ldg(&bias1[c + 1]);
            float v0 = silu(acc[mi][j][0] + bx);
            float v1 = silu(acc[mi][j][1] + by);
            float v2 = silu(acc[mi][j][2] + bx);
            float v3 = silu(acc[mi][j][3] + by);
            int w = c >> 1;
            S[rr * TROW + w]        = pack_bf16(v0, v1);
            S[rr * TROW + 64 + w]   = pack_lo(v0, v1);
            S[rr1 * TROW + w]       = pack_bf16(v2, v3);
            S[rr1 * TROW + 64 + w]  = pack_lo(v2, v3);
            if (!CONCAT) {
                int g0 = base + rr, g1 = base + rr1;
                if (g0 < NN) *(float2*)&H0[(size_t)g0 * 128 + c] = make_float2(v0, v1);
                if (g1 < NN) *(float2*)&H0[(size_t)g1 * 128 + c] = make_float2(v2, v3);
            }
        }
    }
    __syncthreads();

    // ---- stage 2: 2 N-warps x 4 M-warps (FOUT=64, BM=64) ----
    int wx2 = wid & 1, wy2 = wid >> 1;
    int rr = wy2 * 16 + (lane >> 2);
    const unsigned* rp0 = S + rr * TROW;
    const unsigned* rp1 = S + (rr + 8) * TROW;

    float a2[4][4];
    #pragma unroll
    for (int j = 0; j < 4; j++)
        #pragma unroll
        for (int q = 0; q < 4; q++) a2[j][q] = 0.f;

    const uint4* WB = (const uint4*)wfB;
    #pragma unroll
    for (int kl = 0; kl < 128; kl += 16) {
        int ksg = kl >> 4;
        int kp = (kl >> 1) + (lane & 3);
        unsigned ah[4], al[4];
        ah[0] = rp0[kp];      ah[1] = rp1[kp];
        ah[2] = rp0[kp + 4];  ah[3] = rp1[kp + 4];
        al[0] = rp0[64 + kp];     al[1] = rp1[64 + kp];
        al[2] = rp0[64 + kp + 4]; al[3] = rp1[64 + kp + 4];
        #pragma unroll
        for (int j = 0; j < 4; j++) {
            uint4 b = __ldg(&WB[(ksg * 8 + wx2 * 4 + j) * 32 + lane]);
            mma16(a2[j], al, b.x, b.y);
            mma16(a2[j], ah, b.z, b.w);
            mma16(a2[j], ah, b.x, b.y);
        }
    }

    if (CONCAT) {
        const uint4* WC = (const uint4*)wfC;
        int g0 = base + rr;       if (g0 >= NN) g0 = NN - 1;
        int g1 = base + rr + 8;   if (g1 >= NN) g1 = NN - 1;
        #pragma unroll
        for (int kl = 0; kl < 128; kl += 16) {
            int ksg = kl >> 4;
            int k0 = kl + (lane & 3) * 2;
            float2 f0 = *(const float2*)&H0[(size_t)g0 * 128 + k0];
            float2 f1 = *(const float2*)&H0[(size_t)g1 * 128 + k0];
            float2 f2 = *(const float2*)&H0[(size_t)g0 * 128 + k0 + 8];
            float2 f3 = *(const float2*)&H0[(size_t)g1 * 128 + k0 + 8];
            unsigned ah[4], al[4];
            ah[0] = pack_bf16(f0.x, f0.y); al[0] = pack_lo(f0.x, f0.y);
            ah[1] = pack_bf16(f1.x, f1.y); al[1] = pack_lo(f1.x, f1.y);
            ah[2] = pack_bf16(f2.x, f2.y); al[2] = pack_lo(f2.x, f2.y);
            ah[3] = pack_bf16(f3.x, f3.y); al[3] = pack_lo(f3.x, f3.y);
            #pragma unroll
            for (int j = 0; j < 4; j++) {
                uint4 b = __ldg(&WC[(ksg * 8 + wx2 * 4 + j) * 32 + lane]);
                mma16(a2[j], al, b.x, b.y);
                mma16(a2[j], ah, b.z, b.w);
                mma16(a2[j], ah, b.x, b.y);
            }
        }
    }

    // ---- stage-2 epilogue: Y = a2 * dinv ----
    int r0 = base + rr, r1 = r0 + 8;
    float s0 = (r0 < NN) ? rsqrtf((float)deg[r0] + 1.0f) : 0.f;
    float s1 = (r1 < NN) ? rsqrtf((float)deg[r1] + 1.0f) : 0.f;
    #pragma unroll
    for (int j = 0; j < 4; j++) {
        int c = wx2 * 32 + j * 8 + 2 * (lane & 3);
        if (r0 < NN)
            *(float2*)&Y[(size_t)r0 * 64 + c] = make_float2(a2[j][0] * s0, a2[j][1] * s0);
        if (r1 < NN)
            *(float2*)&Y[(size_t)r1 * 64 + c] = make_float2(a2[j][2] * s1, a2[j][3] * s1);
    }
}

// ---------------- 64-wide gather ----------------------------------------------
// MODE 0: out = dinv*(sum z[src] + z[i])
// MODE 1: out = silu(dinv*(sum y[src] + y[i]) + b)
// MODE 2: out = silu(dinv*(sum y[src] + y[i]) + b) * dinv
template <int MODE>
__global__ void __launch_bounds__(256) k_gather64(const float* __restrict__ y,
                                                  const int* __restrict__ off,
                                                  const int* __restrict__ csr,
                                                  const int* __restrict__ deg,
                                                  const float* __restrict__ b,
                                                  float* __restrict__ out) {
    int warp = (blockIdx.x * 256 + threadIdx.x) >> 5;
    int lane = threadIdx.x & 31;
    if (warp >= NN) return;
    int beg = off[warp], end = off[warp + 1];
    float a0, a1;
    {
        float2 t = *(const float2*)(y + (size_t)warp * DD + lane * 2);
        a0 = t.x; a1 = t.y;
    }
    for (int eb = beg; eb < end; eb += 32) {
        int n = end - eb; if (n > 32) n = 32;
        int s = (lane < n) ? __ldg(&csr[eb + lane]) : 0;
        int j = 0;
        for (; j + 4 <= n; j += 4) {
            int s0 = __shfl_sync(0xffffffffu, s, j);
            int s1 = __shfl_sync(0xffffffffu, s, j + 1);
            int s2 = __shfl_sync(0xffffffffu, s, j + 2);
            int s3 = __shfl_sync(0xffffffffu, s, j + 3);
            float2 t0 = *(const float2*)(y + (size_t)s0 * DD + lane * 2);
            float2 t1 = *(const float2*)(y + (size_t)s1 * DD + lane * 2);
            float2 t2 = *(const float2*)(y + (size_t)s2 * DD + lane * 2);
            float2 t3 = *(const float2*)(y + (size_t)s3 * DD + lane * 2);
            a0 += (t0.x + t1.x) + (t2.x + t3.x);
            a1 += (t0.y + t1.y) + (t2.y + t3.y);
        }
        for (; j < n; j++) {
            int sj = __shfl_sync(0xffffffffu, s, j);
            float2 t = *(const float2*)(y + (size_t)sj * DD + lane * 2);
            a0 += t.x; a1 += t.y;
        }
    }
    float di = rsqrtf((float)deg[warp] + 1.0f);
    float o0, o1;
    if (MODE == 0) {
        o0 = di * a0; o1 = di * a1;
    } else {
        float v0 = di * a0 + b[lane * 2];
        float v1 = di * a1 + b[lane * 2 + 1];
        o0 = silu(v0);
        o1 = silu(v1);
        if (MODE == 2) { o0 *= di; o1 *= di; }
    }
    *(float2*)(out + (size_t)warp * DD + lane * 2) = make_float2(o0, o1);
}

// ---------------- launch ----------------------------------------------------
extern "C" void kernel_launch(void* const* d_in, const int* in_sizes, int n_in,
                              void* d_out, int out_size) {
    const float* noise_x   = (const float*)d_in[0];
    const int*   edge      = (const int*)d_in[1];
    const int*   t_in      = (const int*)d_in[2];
    const int*   train_anm = (const int*)d_in[3];
    const int*   train_nrm = (const int*)d_in[4];
    const float* time_w1   = (const float*)d_in[5];
    const float* time_b1   = (const float*)d_in[6];
    const float* time_w2   = (const float*)d_in[7];
    const float* time_b2   = (const float*)d_in[8];
    const float* label_emb = (const float*)d_in[9];
    const float* w0 = (const float*)d_in[10];
    const float* b0 = (const float*)d_in[11];
    const float* w1 = (const float*)d_in[12];
    const float* b1 = (const float*)d_in[13];
    const float* w2 = (const float*)d_in[14];
    const float* b2 = (const float*)d_in[15];
    const float* w3 = (const float*)d_in[16];
    const float* b3 = (const float*)d_in[17];
    float* out = (float*)d_out;

    const int* src = edge;
    const int* dst = edge + EE;
    int n_anm = in_sizes[3];
    int n_nrm = in_sizes[4];
    int n_fl = (n_anm > n_nrm) ? n_anm : n_nrm;

    float *p_temb, *p_ab, *p_h0;
    int *p_deg, *p_flag, *p_off, *p_bsum, *p_cur, *p_csr;
    unsigned *p_wf;
    cudaGetSymbolAddress((void**)&p_temb, g_temb);
    cudaGetSymbolAddress((void**)&p_ab,   g_ab);
    cudaGetSymbolAddress((void**)&p_h0,   g_h0);
    cudaGetSymbolAddress((void**)&p_deg,  g_deg);
    cudaGetSymbolAddress((void**)&p_flag, g_flag);
    cudaGetSymbolAddress((void**)&p_off,  g_off);
    cudaGetSymbolAddress((void**)&p_bsum, g_bsum);
    cudaGetSymbolAddress((void**)&p_cur,  g_cur);
    cudaGetSymbolAddress((void**)&p_csr,  g_csr);
    cudaGetSymbolAddress((void**)&p_wf,   g_wf);

    float* A = p_ab;                 // N x 64
    float* B = p_ab + (size_t)NN * DD;

    const int TB = 256;
    const int GBF = (NN + 63) / 64;
    const int GGATH = (NN * 32 + TB - 1) / TB;

    k_init<<<(NN + TB - 1) / TB, TB>>>(p_deg, p_flag, p_cur);
    k_deg<<<(EE + TB - 1) / TB, TB>>>(dst, p_deg);
    k_wprep<<<6 + (n_fl + 255) / 256, 256>>>(w0, w1, w2, w3, p_wf,
                        t_in, time_w1, time_b1, time_w2, time_b2, p_temb,
                        train_anm, n_anm, train_nrm, n_nrm, p_flag);
    k_z0<<<(NN * 16 + TB - 1) / TB, TB>>>(noise_x, label_emb, p_temb, p_flag, p_deg, A);

    // ---- CSR build ----
    k_scan1<<<NB, SB>>>(p_deg, p_off, p_bsum);
    k_scan3m<<<(NN + 255) / 256, 256>>>(p_off, p_bsum);
    k_fill<<<(EE + TB - 1) / TB, TB>>>(src, dst, p_off, p_cur, p_csr);

    // ---- layer 0 aggregate-before: B = dinv*(agg(A)+A) ----
    k_gather64<0><<<GGATH, TB>>>(A, p_off, p_csr, p_deg, 0, B);

    // ---- F01: h0 = silu(B*W0+b0); A = (h0*W1)*dinv ----
    k_fused<false><<<GBF, 256>>>(B, p_wf + 0 * WFW, p_wf + 1 * WFW, 0, p_h0, A, p_deg, b0);

    // ---- layer-1 aggregate-after + layer-2 pre-scale ----
    k_gather64<2><<<GGATH, TB>>>(A, p_off, p_csr, p_deg, b1, B);   // z2
    // ---- layer 2 aggregate-before ----
    k_gather64<0><<<GGATH, TB>>>(B, p_off, p_csr, p_deg, 0, A);    // g2

    // ---- F23: T = silu(A*W2+b2); B = (T*W3a + h0*W3b)*dinv ----
    k_fused<true><<<GBF, 256>>>(A, p_wf + 2 * WFW, p_wf + 3 * WFW, p_wf + 4 * WFW,
                                p_h0, B, p_deg, b2);

    // ---- final aggregate ----
    k_gather64<1><<<GGATH, TB>>>(B, p_off, p_csr, p_deg, b3, out);
}